// round 1
// baseline (speedup 1.0000x reference)
#include <cuda_runtime.h>
#include <cstdint>

#define KK 16
#define FF 32
#define NT 64
#define NTHREADS 128
#define NWARP (NTHREADS/32)

__device__ __forceinline__ float warpsum(float v){
  #pragma unroll
  for (int o = 16; o > 0; o >>= 1) v += __shfl_xor_sync(0xffffffffu, v, o);
  return v;
}

// Detect whether an index array is int64 (odd 32-bit words all zero for values < 2^31)
// or int32. Values are node ids < 1e6, and sel arrays are permutation chunks
// (distinct), so four simultaneous zeros under int32 interpretation is impossible.
__device__ __forceinline__ int is64_flag(const void* p){
  const unsigned int* u = (const unsigned int*)p;
  return ((u[1] | u[3] | u[5] | u[7]) == 0u) ? 1 : 0;
}

__device__ __forceinline__ long long ldidx(const void* p, long long i, int is64){
  if (is64) return ((const long long*)p)[i];
  return (long long)((const int*)p)[i];
}

template<int DEG>
__global__ void __launch_bounds__(NTHREADS) score_kernel(
    const float* __restrict__ x,
    const void* __restrict__ sel,
    const void* __restrict__ nei,
    const float* __restrict__ Wf,
    const float* __restrict__ Wn,
    float* __restrict__ out,
    int Nd)
{
  constexpr int L  = (1 + DEG) * FF;   // extended feature length per node
  constexpr int LP = L + 4;            // padded stride (16B-aligned, bank-skewed)

  extern __shared__ float smem[];
  float* Xs = smem;                        // NT * LP
  float* Ws = smem + NT * LP;              // KK * LP
  float* Ss = smem + NT * LP + KK * LP;    // NT * KK  (score staging)

  const int tid  = threadIdx.x;
  const int w    = tid >> 5;
  const int lane = tid & 31;
  const int tile = blockIdx.x * NT;
  const int count = min(NT, Nd - tile);
  const int s64 = is64_flag(sel);
  const int n64 = is64_flag(nei);

  // ---- Phase 0: normalize weights into SMEM (1/DEG folded into neighbor rows)
  {
    constexpr int RW = KK * (1 + DEG);
    for (int r = w; r < RW; r += NWARP){
      const int k = r / (1 + DEG), s = r % (1 + DEG);
      float v = (s == 0) ? Wf[k * FF + lane]
                         : Wn[(k * DEG + (s - 1)) * FF + lane];
      const float ss = warpsum(v * v);
      float sc = rsqrtf(ss);
      if (s) sc *= (1.0f / DEG);
      Ws[k * LP + s * FF + lane] = v * sc;
    }
  }

  // ---- Phase 1: gather + L2-normalize node rows into SMEM (4-row batches -> MLP>=4)
  {
    constexpr int R   = NT * (1 + DEG);
    constexpr int RPW = R / NWARP;       // divisible for all DEG
    const int rb = w * RPW, re = rb + RPW;
    for (int r0 = rb; r0 < re; r0 += 4){
      float v[4];
      #pragma unroll
      for (int i = 0; i < 4; i++){
        const int r = r0 + i;
        const int n = r / (1 + DEG), s = r % (1 + DEG);
        const bool valid = (n < count);
        long long g = 0;
        if (valid){
          g = (s == 0) ? ldidx(sel, tile + n, s64)
                       : ldidx(nei, (long long)(tile + n) * DEG + (s - 1), n64);
        }
        v[i] = valid ? x[g * FF + lane] : 0.0f;
      }
      #pragma unroll
      for (int i = 0; i < 4; i++){
        const int r = r0 + i;
        const int n = r / (1 + DEG), s = r % (1 + DEG);
        const float ss = warpsum(v[i] * v[i]);
        const float sc = (ss > 0.0f) ? rsqrtf(ss) : 0.0f;
        Xs[n * LP + s * FF + lane] = v[i] * sc;
      }
    }
  }
  __syncthreads();

  // ---- Phase 2: register-tiled GEMM: thread = 4 nodes x 2 kernels, float4 over f
  {
    const int kg = tid & 7;    // 8 k-groups of 2
    const int ng = tid >> 3;   // 16 node-groups of 4
    float acc[4][2];
    #pragma unroll
    for (int i = 0; i < 4; i++)
      #pragma unroll
      for (int j = 0; j < 2; j++) acc[i][j] = 0.0f;

    #pragma unroll 4
    for (int ff = 0; ff < L; ff += 4){
      float4 xv[4], wv[2];
      #pragma unroll
      for (int i = 0; i < 4; i++)
        xv[i] = *(const float4*)&Xs[(ng * 4 + i) * LP + ff];
      #pragma unroll
      for (int j = 0; j < 2; j++)
        wv[j] = *(const float4*)&Ws[(kg * 2 + j) * LP + ff];
      #pragma unroll
      for (int i = 0; i < 4; i++)
        #pragma unroll
        for (int j = 0; j < 2; j++)
          acc[i][j] += xv[i].x * wv[j].x + xv[i].y * wv[j].y
                     + xv[i].z * wv[j].z + xv[i].w * wv[j].w;
    }
    #pragma unroll
    for (int i = 0; i < 4; i++)
      #pragma unroll
      for (int j = 0; j < 2; j++)
        Ss[(ng * 4 + i) * KK + kg * 2 + j] = acc[i][j];
  }
  __syncthreads();

  // ---- Phase 3: write full 256B output row per node (zeros + score block), coalesced
  {
    const int c0  = lane * 2;
    const int blk = c0 >> 4;
    for (int n = w; n < count; n += NWARP){
      const long long node = ldidx(sel, tile + n, s64);
      float2 v;
      if (blk == DEG - 1){
        const float2 sv = *(const float2*)&Ss[n * KK + (c0 & 15)];
        v = sv;
      } else {
        v.x = 0.0f; v.y = 0.0f;
      }
      *(float2*)&out[(long long)node * 64 + c0] = v;
    }
  }
}

static inline int smem_bytes(int deg){
  const int LP = (1 + deg) * FF + 4;
  return ((NT + KK) * LP + NT * KK) * (int)sizeof(float);
}

extern "C" void kernel_launch(void* const* d_in, const int* in_sizes, int n_in,
                              void* d_out, int out_size)
{
  const float* x = (const float*)d_in[0];
  const void *sel[4], *nei[4];
  const float *Wf[4], *Wn[4];
  int Nd[4];

  if (in_sizes[1] == 512){
    // reference-signature order: x, (Wf,Wn)x4, sel1..4, nei1..4
    for (int d = 0; d < 4; d++){
      Wf[d]  = (const float*)d_in[1 + 2 * d];
      Wn[d]  = (const float*)d_in[2 + 2 * d];
      sel[d] = d_in[9 + d];
      nei[d] = d_in[13 + d];
      Nd[d]  = in_sizes[9 + d];
    }
  } else {
    // setup_inputs dict order: x, then (sel, nei, Wf, Wn) per degree
    int b = 1;
    for (int d = 0; d < 4; d++){
      sel[d] = d_in[b + 0];
      nei[d] = d_in[b + 1];
      Wf[d]  = (const float*)d_in[b + 2];
      Wn[d]  = (const float*)d_in[b + 3];
      Nd[d]  = in_sizes[b + 0];
      b += 4;
    }
  }

  float* out = (float*)d_out;

  // deg3/deg4 tiles exceed the 48KB static limit -> opt in to large dynamic SMEM.
  cudaFuncSetAttribute(score_kernel<1>, cudaFuncAttributeMaxDynamicSharedMemorySize, smem_bytes(1));
  cudaFuncSetAttribute(score_kernel<2>, cudaFuncAttributeMaxDynamicSharedMemorySize, smem_bytes(2));
  cudaFuncSetAttribute(score_kernel<3>, cudaFuncAttributeMaxDynamicSharedMemorySize, smem_bytes(3));
  cudaFuncSetAttribute(score_kernel<4>, cudaFuncAttributeMaxDynamicSharedMemorySize, smem_bytes(4));

  score_kernel<1><<<(Nd[0] + NT - 1) / NT, NTHREADS, smem_bytes(1)>>>(
      x, sel[0], nei[0], Wf[0], Wn[0], out, Nd[0]);
  score_kernel<2><<<(Nd[1] + NT - 1) / NT, NTHREADS, smem_bytes(2)>>>(
      x, sel[1], nei[1], Wf[1], Wn[1], out, Nd[1]);
  score_kernel<3><<<(Nd[2] + NT - 1) / NT, NTHREADS, smem_bytes(3)>>>(
      x, sel[2], nei[2], Wf[2], Wn[2], out, Nd[2]);
  score_kernel<4><<<(Nd[3] + NT - 1) / NT, NTHREADS, smem_bytes(4)>>>(
      x, sel[3], nei[3], Wf[3], Wn[3], out, Nd[3]);
}

// round 3
// speedup vs baseline: 1.6211x; 1.6211x over previous
#include <cuda_runtime.h>
#include <cstdint>
#include <cstring>

#define KK 16
#define FF 32
#define NT 64
#define NTHREADS 128
#define NWARP (NTHREADS/32)

__device__ __forceinline__ float warpsum(float v){
  #pragma unroll
  for (int o = 16; o > 0; o >>= 1) v += __shfl_xor_sync(0xffffffffu, v, o);
  return v;
}

// sum within aligned 8-lane groups
__device__ __forceinline__ float grp8sum(float v){
  v += __shfl_xor_sync(0xffffffffu, v, 1);
  v += __shfl_xor_sync(0xffffffffu, v, 2);
  v += __shfl_xor_sync(0xffffffffu, v, 4);
  return v;
}

// packed f32x2 FMA (sm_100+; emits FFMA2 — not reachable from C++)
__device__ __forceinline__ unsigned long long ffma2(unsigned long long a,
                                                    unsigned long long b,
                                                    unsigned long long c){
  unsigned long long d;
  asm("fma.rn.f32x2 %0, %1, %2, %3;" : "=l"(d) : "l"(a), "l"(b), "l"(c));
  return d;
}

__device__ __forceinline__ float2 unpack2(unsigned long long a){
  float2 f;
  asm("mov.b64 {%0, %1}, %2;" : "=f"(f.x), "=f"(f.y) : "l"(a));
  return f;
}

// int64 vs int32 index array detection (node ids < 2^31; sel entries distinct
// permutation values, so 4 simultaneous zeros under int32 view is impossible)
__device__ __forceinline__ int is64_flag(const void* p){
  const unsigned int* u = (const unsigned int*)p;
  return ((u[1] | u[3] | u[5] | u[7]) == 0u) ? 1 : 0;
}
__device__ __forceinline__ long long ldidx(const void* p, long long i, int is64){
  if (is64) return ((const long long*)p)[i];
  return (long long)((const int*)p)[i];
}

template<int DEG>
__global__ void __launch_bounds__(NTHREADS, 4) score_kernel(
    const float* __restrict__ x,
    const void* __restrict__ sel,
    const void* __restrict__ nei,
    const float* __restrict__ Wf,
    const float* __restrict__ Wn,
    float* __restrict__ out,
    int Nd)
{
  constexpr int RPG = 1 + DEG;       // rows (focal + neighbors) per node
  constexpr int L   = RPG * FF;      // extended feature length
  constexpr int LP  = L + 4;         // padded stride: 16B-aligned, 4*LP%32==16 -> <=2-way LDS conflict

  extern __shared__ float smem[];
  float* Xs = smem;                       // NT * LP
  float* Ws = smem + NT * LP;             // KK * LP
  int*   Is = (int*)(smem + NT * LP + KK * LP);  // NT node ids

  const int tid  = threadIdx.x;
  const int w    = tid >> 5;
  const int lane = tid & 31;
  const int tile = blockIdx.x * NT;
  const int count = min(NT, Nd - tile);
  const int s64 = is64_flag(sel);
  const int n64 = is64_flag(nei);

  // ---- Phase 0: normalize weights into SMEM (1/DEG folded into neighbor rows)
  {
    constexpr int RW = KK * RPG;
    for (int r = w; r < RW; r += NWARP){
      const int k = r / RPG, s = r % RPG;
      float v = (s == 0) ? Wf[k * FF + lane]
                         : Wn[(k * DEG + (s - 1)) * FF + lane];
      const float ss = warpsum(v * v);
      float sc = rsqrtf(ss);
      if (s) sc *= (1.0f / DEG);
      Ws[k * LP + s * FF + lane] = v * sc;
    }
  }

  // ---- Phase 1: gather + L2-normalize node rows into SMEM.
  // 8 lanes per row (float4 each), 4 rows per warp-instr, pipelined 4-deep
  // (16 rows per macro-iteration) for MLP.
  {
    constexpr int R   = NT * RPG;
    constexpr int RPW = R / NWARP;        // 32/48/64/80 — all divisible by 16
    const int rb = w * RPW;
    const int c  = lane & 7;
    const int rg = lane >> 3;

    #pragma unroll 1
    for (int r0 = rb; r0 < rb + RPW; r0 += 16){
      long long g[4]; int nn[4], ss_[4]; bool val[4];
      #pragma unroll
      for (int u = 0; u < 4; u++){
        const int r = r0 + u * 4 + rg;
        nn[u] = r / RPG; ss_[u] = r - nn[u] * RPG;
        val[u] = (nn[u] < count);
        g[u] = 0;
        if (val[u]){
          g[u] = (ss_[u] == 0) ? ldidx(sel, tile + nn[u], s64)
                               : ldidx(nei, (long long)(tile + nn[u]) * DEG + (ss_[u] - 1), n64);
        }
      }
      float4 v[4];
      #pragma unroll
      for (int u = 0; u < 4; u++){
        v[u] = val[u] ? *(const float4*)&x[g[u] * FF + c * 4]
                      : make_float4(0.f, 0.f, 0.f, 0.f);
      }
      #pragma unroll
      for (int u = 0; u < 4; u++){
        const float ssq = grp8sum(v[u].x * v[u].x + v[u].y * v[u].y
                                + v[u].z * v[u].z + v[u].w * v[u].w);
        const float sc = (ssq > 0.0f) ? rsqrtf(ssq) : 0.0f;
        float4 o; o.x = v[u].x * sc; o.y = v[u].y * sc; o.z = v[u].z * sc; o.w = v[u].w * sc;
        *(float4*)&Xs[nn[u] * LP + ss_[u] * FF + c * 4] = o;
        if (ss_[u] == 0 && c == 0) Is[nn[u]] = (int)g[u];
      }
    }
  }
  __syncthreads();

  // ---- Phase 2a: zero-fill the 48 non-score columns of each node's output row.
  // lanes 0..11 write one float4 each (columns skip the score block).
  {
    const int col = lane * 4 + ((lane * 4 >= 16 * (DEG - 1)) ? 16 : 0);
    const bool wr = (lane < 12);
    const float4 z = make_float4(0.f, 0.f, 0.f, 0.f);
    for (int n = w; n < count; n += NWARP){
      const long long node = Is[n];
      if (wr) *(float4*)&out[node * 64 + col] = z;
    }
  }

  // ---- Phase 2b: register-tiled GEMM with packed f32x2 FMA.
  // thread = 4 nodes (ng) x 2 kernels (kg); inner step 4 features = 2 FFMA2 per (i,j).
  {
    const int kg = tid & 7;
    const int ng = tid >> 3;
    unsigned long long acc[4][2];
    #pragma unroll
    for (int i = 0; i < 4; i++)
      #pragma unroll
      for (int j = 0; j < 2; j++) acc[i][j] = 0ULL;

    const float* xb = Xs + (ng * 4) * LP;
    const float* wb = Ws + (kg * 2) * LP;

    #pragma unroll 2
    for (int ff = 0; ff < L; ff += 4){
      ulonglong2 xv[4], wv[2];
      #pragma unroll
      for (int i = 0; i < 4; i++)
        xv[i] = *(const ulonglong2*)(xb + i * LP + ff);
      #pragma unroll
      for (int j = 0; j < 2; j++)
        wv[j] = *(const ulonglong2*)(wb + j * LP + ff);
      #pragma unroll
      for (int i = 0; i < 4; i++){
        #pragma unroll
        for (int j = 0; j < 2; j++){
          acc[i][j] = ffma2(xv[i].x, wv[j].x, acc[i][j]);
          acc[i][j] = ffma2(xv[i].y, wv[j].y, acc[i][j]);
        }
      }
    }

    // scatter scores: per node a float2 at columns [16*(DEG-1)+kg*2, +2)
    #pragma unroll
    for (int i = 0; i < 4; i++){
      const int n = ng * 4 + i;
      if (n < count){
        const float2 a0 = unpack2(acc[i][0]);
        const float2 a1 = unpack2(acc[i][1]);
        float2 sv; sv.x = a0.x + a0.y; sv.y = a1.x + a1.y;
        const long long node = Is[n];
        *(float2*)&out[node * 64 + (DEG - 1) * 16 + kg * 2] = sv;
      }
    }
  }
}

static inline int smem_bytes(int deg){
  const int LP = (1 + deg) * FF + 4;
  return ((NT + KK) * LP) * (int)sizeof(float) + NT * (int)sizeof(int);
}

extern "C" void kernel_launch(void* const* d_in, const int* in_sizes, int n_in,
                              void* d_out, int out_size)
{
  const float* x = (const float*)d_in[0];
  const void *sel[4], *nei[4];
  const float *Wf[4], *Wn[4];
  int Nd[4];

  if (in_sizes[1] == 512){
    // reference-signature order: x, (Wf,Wn)x4, sel1..4, nei1..4
    for (int d = 0; d < 4; d++){
      Wf[d]  = (const float*)d_in[1 + 2 * d];
      Wn[d]  = (const float*)d_in[2 + 2 * d];
      sel[d] = d_in[9 + d];
      nei[d] = d_in[13 + d];
      Nd[d]  = in_sizes[9 + d];
    }
  } else {
    // setup_inputs dict order: x, then (sel, nei, Wf, Wn) per degree
    int b = 1;
    for (int d = 0; d < 4; d++){
      sel[d] = d_in[b + 0];
      nei[d] = d_in[b + 1];
      Wf[d]  = (const float*)d_in[b + 2];
      Wn[d]  = (const float*)d_in[b + 3];
      Nd[d]  = in_sizes[b + 0];
      b += 4;
    }
  }

  float* out = (float*)d_out;

  cudaFuncSetAttribute(score_kernel<1>, cudaFuncAttributeMaxDynamicSharedMemorySize, smem_bytes(1));
  cudaFuncSetAttribute(score_kernel<2>, cudaFuncAttributeMaxDynamicSharedMemorySize, smem_bytes(2));
  cudaFuncSetAttribute(score_kernel<3>, cudaFuncAttributeMaxDynamicSharedMemorySize, smem_bytes(3));
  cudaFuncSetAttribute(score_kernel<4>, cudaFuncAttributeMaxDynamicSharedMemorySize, smem_bytes(4));

  score_kernel<1><<<(Nd[0] + NT - 1) / NT, NTHREADS, smem_bytes(1)>>>(
      x, sel[0], nei[0], Wf[0], Wn[0], out, Nd[0]);
  score_kernel<2><<<(Nd[1] + NT - 1) / NT, NTHREADS, smem_bytes(2)>>>(
      x, sel[1], nei[1], Wf[1], Wn[1], out, Nd[1]);
  score_kernel<3><<<(Nd[2] + NT - 1) / NT, NTHREADS, smem_bytes(3)>>>(
      x, sel[2], nei[2], Wf[2], Wn[2], out, Nd[2]);
  score_kernel<4><<<(Nd[3] + NT - 1) / NT, NTHREADS, smem_bytes(4)>>>(
      x, sel[3], nei[3], Wf[3], Wn[3], out, Nd[3]);
}